// round 1
// baseline (speedup 1.0000x reference)
#include <cuda_runtime.h>

#define NODES 100000
#define NPAD  100032     // 1563 * 64
#define EDGES 1600000
#define GRID_M 1563
#define CHUNK 1024
#define NCHUNK 98        // ceil(100000/1024)

// ---------------- scratch (device globals; no allocation) ----------------
__device__ int   d_deg[NODES];
__device__ int   d_cursor[NODES];
__device__ int   d_row[NODES + 1];
__device__ int   d_csr[EDGES];
__device__ int   d_csums[NCHUNK];
__device__ float d_mean1[NPAD * 128];   // mean-aggregated x
__device__ float d_h1[NPAD * 128];      // layer1 output
__device__ float d_pl[NPAD * 64];       // h1 @ W2l^T (to be aggregated)
__device__ float d_pr[NPAD * 64];       // h1 @ W2r^T (self term)
__device__ float d_wt1[256 * 128];      // transposed [W1l; W1r]  (k-major)
__device__ float d_wt2[128 * 128];      // transposed [W2l | W2r] (k-major)

// ---------------- CSR build ----------------
__global__ void k_zero() {
    int i = blockIdx.x * blockDim.x + threadIdx.x;
    if (i < NODES) { d_deg[i] = 0; d_cursor[i] = 0; }
}

__global__ void k_hist(const int* __restrict__ dst) {
    int i = blockIdx.x * blockDim.x + threadIdx.x;
    if (i < EDGES) atomicAdd(&d_deg[dst[i]], 1);
}

// per-chunk exclusive scan of deg -> d_row, chunk totals -> d_csums
__global__ void k_scan1() {
    __shared__ int ws[32];
    int i = blockIdx.x * CHUNK + threadIdx.x;
    int lane = threadIdx.x & 31, wid = threadIdx.x >> 5;
    int v = (i < NODES) ? d_deg[i] : 0;
    int x = v;
    #pragma unroll
    for (int o = 1; o < 32; o <<= 1) {
        int y = __shfl_up_sync(0xffffffffu, x, o);
        if (lane >= o) x += y;
    }
    if (lane == 31) ws[wid] = x;
    __syncthreads();
    if (wid == 0) {
        int s = ws[lane];
        #pragma unroll
        for (int o = 1; o < 32; o <<= 1) {
            int y = __shfl_up_sync(0xffffffffu, s, o);
            if (lane >= o) s += y;
        }
        ws[lane] = s;
    }
    __syncthreads();
    int incl = x + (wid > 0 ? ws[wid - 1] : 0);
    if (i < NODES) d_row[i] = incl - v;       // exclusive within chunk
    if (threadIdx.x == CHUNK - 1) d_csums[blockIdx.x] = incl;
}

__global__ void k_scan2() {
    if (threadIdx.x == 0) {
        int run = 0;
        for (int c = 0; c < NCHUNK; c++) { int t = d_csums[c]; d_csums[c] = run; run += t; }
    }
}

__global__ void k_scan3() {
    int i = blockIdx.x * blockDim.x + threadIdx.x;
    if (i < NODES) d_row[i] += d_csums[i / CHUNK];
    if (i == 0) d_row[NODES] = EDGES;
}

__global__ void k_scatter(const int* __restrict__ src, const int* __restrict__ dst) {
    int i = blockIdx.x * blockDim.x + threadIdx.x;
    if (i < EDGES) {
        int d = dst[i];
        int o = atomicAdd(&d_cursor[d], 1);
        d_csr[d_row[d] + o] = src[i];
    }
}

// ---------------- weight pre-transpose (tiny, once per launch) ----------------
__global__ void k_wt(const float* __restrict__ W1l, const float* __restrict__ W1r,
                     const float* __restrict__ W2l, const float* __restrict__ W2r) {
    int i = blockIdx.x * blockDim.x + threadIdx.x;
    if (i < 256 * 128) {
        int k = i >> 7, n = i & 127;
        d_wt1[i] = (k < 128) ? W1l[n * 128 + k] : W1r[n * 128 + (k - 128)];
    }
    if (i < 128 * 128) {
        int k = i >> 7, n = i & 127;
        d_wt2[i] = (n < 64) ? W2l[n * 128 + k] : W2r[(n - 64) * 128 + k];
    }
}

// ---------------- layer1 aggregation: warp per node, 128-dim rows ----------------
__global__ void __launch_bounds__(256) k_agg1(const float* __restrict__ x) {
    int gw = (blockIdx.x * blockDim.x + threadIdx.x) >> 5;
    int lane = threadIdx.x & 31;
    if (gw >= NODES) return;
    int s0 = d_row[gw], s1 = d_row[gw + 1];
    const float4* x4 = (const float4*)x;
    float4 acc = make_float4(0.f, 0.f, 0.f, 0.f);
    for (int base = s0; base < s1; base += 32) {
        int rem = s1 - base;
        int sv = (lane < rem) ? d_csr[base + lane] : 0;
        int cnt = rem < 32 ? rem : 32;
        int j = 0;
        for (; j + 4 <= cnt; j += 4) {
            int sa = __shfl_sync(0xffffffffu, sv, j);
            int sb = __shfl_sync(0xffffffffu, sv, j + 1);
            int sc = __shfl_sync(0xffffffffu, sv, j + 2);
            int sd = __shfl_sync(0xffffffffu, sv, j + 3);
            float4 va = x4[sa * 32 + lane];
            float4 vb = x4[sb * 32 + lane];
            float4 vc = x4[sc * 32 + lane];
            float4 vd = x4[sd * 32 + lane];
            acc.x += va.x + vb.x + vc.x + vd.x;
            acc.y += va.y + vb.y + vc.y + vd.y;
            acc.z += va.z + vb.z + vc.z + vd.z;
            acc.w += va.w + vb.w + vc.w + vd.w;
        }
        for (; j < cnt; j++) {
            int s = __shfl_sync(0xffffffffu, sv, j);
            float4 v = x4[s * 32 + lane];
            acc.x += v.x; acc.y += v.y; acc.z += v.z; acc.w += v.w;
        }
    }
    int deg = s1 - s0;
    float sc = 1.0f / (float)(deg > 1 ? deg : 1);
    float4 m = make_float4(acc.x * sc, acc.y * sc, acc.z * sc, acc.w * sc);
    ((float4*)d_mean1)[gw * 32 + lane] = m;
}

// ---------------- GEMM1: h1 = relu([mean1 | x] @ [W1l;W1r]^T + b1) ----------------
// block: 256 threads = 8 warps; 64 nodes x 128 outs; warp w -> nodes 8w..8w+7,
// lane l -> outs 4l..4l+3. K = 256.
extern __shared__ float smbuf[];
__global__ void __launch_bounds__(256) k_gemm1(const float* __restrict__ x,
                                               const float* __restrict__ b1) {
    float* Wt = smbuf;                 // 256*128
    float* As = smbuf + 256 * 128;     // 32*65 (padded)
    int tid = threadIdx.x;
    int lane = tid & 31, w = tid >> 5;
    int nb = blockIdx.x * 64;

    for (int i = tid; i < 256 * 128; i += 256) Wt[i] = d_wt1[i];

    float4 acc[8];
    #pragma unroll
    for (int j = 0; j < 8; j++) acc[j] = make_float4(0.f, 0.f, 0.f, 0.f);

    for (int kb = 0; kb < 8; kb++) {
        #pragma unroll
        for (int t = tid; t < 2048; t += 256) {
            int row = t >> 5, kk = t & 31;
            int kg = kb * 32 + kk;
            int node = nb + row;
            float v;
            if (kg < 128) v = d_mean1[node * 128 + kg];
            else {
                int nc = node < NODES ? node : NODES - 1;
                v = x[nc * 128 + (kg - 128)];
            }
            As[kk * 65 + row] = v;
        }
        __syncthreads();
        #pragma unroll 8
        for (int kk = 0; kk < 32; kk++) {
            float4 wv = *(const float4*)(Wt + (kb * 32 + kk) * 128 + 4 * lane);
            const float* ap = As + kk * 65 + w * 8;
            #pragma unroll
            for (int j = 0; j < 8; j++) {
                float a = ap[j];
                acc[j].x += a * wv.x; acc[j].y += a * wv.y;
                acc[j].z += a * wv.z; acc[j].w += a * wv.w;
            }
        }
        __syncthreads();
    }

    float4 bv = *(const float4*)(b1 + 4 * lane);
    #pragma unroll
    for (int j = 0; j < 8; j++) {
        int node = nb + w * 8 + j;
        float4 r;
        r.x = fmaxf(acc[j].x + bv.x, 0.f);
        r.y = fmaxf(acc[j].y + bv.y, 0.f);
        r.z = fmaxf(acc[j].z + bv.z, 0.f);
        r.w = fmaxf(acc[j].w + bv.w, 0.f);
        *(float4*)(d_h1 + node * 128 + 4 * lane) = r;
    }
}

// ---------------- GEMM2: [p_l | p_r] = h1 @ [W2l | W2r]^T  (K=128, N=128) ----------------
__global__ void __launch_bounds__(256) k_gemm2() {
    float* Wt = smbuf;                 // 128*128
    float* As = smbuf + 128 * 128;     // 32*65
    int tid = threadIdx.x;
    int lane = tid & 31, w = tid >> 5;
    int nb = blockIdx.x * 64;

    for (int i = tid; i < 128 * 128; i += 256) Wt[i] = d_wt2[i];

    float4 acc[8];
    #pragma unroll
    for (int j = 0; j < 8; j++) acc[j] = make_float4(0.f, 0.f, 0.f, 0.f);

    for (int kb = 0; kb < 4; kb++) {
        #pragma unroll
        for (int t = tid; t < 2048; t += 256) {
            int row = t >> 5, kk = t & 31;
            int kg = kb * 32 + kk;
            int node = nb + row;
            As[kk * 65 + row] = d_h1[node * 128 + kg];
        }
        __syncthreads();
        #pragma unroll 8
        for (int kk = 0; kk < 32; kk++) {
            float4 wv = *(const float4*)(Wt + (kb * 32 + kk) * 128 + 4 * lane);
            const float* ap = As + kk * 65 + w * 8;
            #pragma unroll
            for (int j = 0; j < 8; j++) {
                float a = ap[j];
                acc[j].x += a * wv.x; acc[j].y += a * wv.y;
                acc[j].z += a * wv.z; acc[j].w += a * wv.w;
            }
        }
        __syncthreads();
    }

    #pragma unroll
    for (int j = 0; j < 8; j++) {
        int node = nb + w * 8 + j;
        if (lane < 16) ((float4*)d_pl)[node * 16 + lane] = acc[j];
        else           ((float4*)d_pr)[node * 16 + (lane - 16)] = acc[j];
    }
}

// ---------------- layer2 aggregation + bias + relu + FC, fused ----------------
// warp per node; lane holds dims (2l, 2l+1) of the 64-dim hidden.
__global__ void __launch_bounds__(256) k_agg2fc(const float* __restrict__ b2,
                                                const float* __restrict__ Wfc,
                                                const float* __restrict__ bfc,
                                                float* __restrict__ out) {
    int gw = (blockIdx.x * blockDim.x + threadIdx.x) >> 5;
    int lane = threadIdx.x & 31;
    if (gw >= NODES) return;
    int s0 = d_row[gw], s1 = d_row[gw + 1];
    const float2* pl2 = (const float2*)d_pl;
    float a0 = 0.f, a1 = 0.f;
    for (int base = s0; base < s1; base += 32) {
        int rem = s1 - base;
        int sv = (lane < rem) ? d_csr[base + lane] : 0;
        int cnt = rem < 32 ? rem : 32;
        int j = 0;
        for (; j + 4 <= cnt; j += 4) {
            int sa = __shfl_sync(0xffffffffu, sv, j);
            int sb = __shfl_sync(0xffffffffu, sv, j + 1);
            int sc = __shfl_sync(0xffffffffu, sv, j + 2);
            int sd = __shfl_sync(0xffffffffu, sv, j + 3);
            float2 va = pl2[sa * 32 + lane];
            float2 vb = pl2[sb * 32 + lane];
            float2 vc = pl2[sc * 32 + lane];
            float2 vd = pl2[sd * 32 + lane];
            a0 += va.x + vb.x + vc.x + vd.x;
            a1 += va.y + vb.y + vc.y + vd.y;
        }
        for (; j < cnt; j++) {
            int s = __shfl_sync(0xffffffffu, sv, j);
            float2 v = pl2[s * 32 + lane];
            a0 += v.x; a1 += v.y;
        }
    }
    int deg = s1 - s0;
    float sc = 1.0f / (float)(deg > 1 ? deg : 1);
    float2 pr = ((const float2*)d_pr)[gw * 32 + lane];
    float2 bb = ((const float2*)b2)[lane];
    float h0 = fmaxf(a0 * sc + pr.x + bb.x, 0.f);
    float h1 = fmaxf(a1 * sc + pr.y + bb.y, 0.f);
    float2 w0 = ((const float2*)Wfc)[lane];        // row 0 of Wfc [2][64]
    float2 w1 = ((const float2*)Wfc)[32 + lane];   // row 1
    float o0 = h0 * w0.x + h1 * w0.y;
    float o1 = h0 * w1.x + h1 * w1.y;
    #pragma unroll
    for (int o = 16; o; o >>= 1) {
        o0 += __shfl_xor_sync(0xffffffffu, o0, o);
        o1 += __shfl_xor_sync(0xffffffffu, o1, o);
    }
    if (lane == 0) {
        out[2 * gw]     = o0 + bfc[0];
        out[2 * gw + 1] = o1 + bfc[1];
    }
}

// ---------------- launch ----------------
extern "C" void kernel_launch(void* const* d_in, const int* in_sizes, int n_in,
                              void* d_out, int out_size) {
    const float* x   = (const float*)d_in[0];
    const int*   ei  = (const int*)d_in[1];
    const float* W1l = (const float*)d_in[2];
    const float* b1  = (const float*)d_in[3];
    const float* W1r = (const float*)d_in[4];
    const float* W2l = (const float*)d_in[5];
    const float* b2  = (const float*)d_in[6];
    const float* W2r = (const float*)d_in[7];
    const float* Wfc = (const float*)d_in[8];
    const float* bfc = (const float*)d_in[9];
    float* out = (float*)d_out;
    const int* src = ei;
    const int* dst = ei + EDGES;

    const int SMEM1 = (256 * 128 + 32 * 65) * 4;   // 139,392 B
    const int SMEM2 = (128 * 128 + 32 * 65) * 4;   //  73,856 B
    cudaFuncSetAttribute(k_gemm1, cudaFuncAttributeMaxDynamicSharedMemorySize, SMEM1);
    cudaFuncSetAttribute(k_gemm2, cudaFuncAttributeMaxDynamicSharedMemorySize, SMEM2);

    k_zero<<<(NODES + 255) / 256, 256>>>();
    k_wt<<<(256 * 128 + 255) / 256, 256>>>(W1l, W1r, W2l, W2r);
    k_hist<<<(EDGES + 255) / 256, 256>>>(dst);
    k_scan1<<<NCHUNK, CHUNK>>>();
    k_scan2<<<1, 32>>>();
    k_scan3<<<(NODES + 255) / 256, 256>>>();
    k_scatter<<<(EDGES + 255) / 256, 256>>>(src, dst);
    k_agg1<<<(NODES * 32 + 255) / 256, 256>>>(x);
    k_gemm1<<<GRID_M, 256, SMEM1>>>(x, b1);
    k_gemm2<<<GRID_M, 256, SMEM2>>>();
    k_agg2fc<<<(NODES * 32 + 255) / 256, 256>>>(b2, Wfc, bfc, out);
}

// round 2
// speedup vs baseline: 2.3826x; 2.3826x over previous
#include <cuda_runtime.h>
#include <cstdint>

#define NODES 100000
#define EDGES 1600000
#define TILES 782            // 782 * 128 = 100096
#define NPAD  100096
#define CHUNK 1024
#define NCHUNK 98            // ceil(100000/1024)

// ---------------- scratch (device globals; no allocation) ----------------
__device__ int   d_deg[NODES];
__device__ int   d_cursor[NODES];
__device__ int   d_row[NODES + 1];
__device__ int   d_csr[EDGES];
__device__ int   d_csums[NCHUNK];
__device__ float d_mean1[NPAD * 128];   // mean-aggregated x (padded rows stay 0)
__device__ float d_h1[NPAD * 128];      // layer1 output
__device__ float d_pl[NPAD * 64];       // h1 @ W2l^T (to be aggregated)
__device__ float d_pr[NPAD * 64];       // h1 @ W2r^T (self term)
__device__ float d_wt1[256 * 128];      // transposed [W1l; W1r]  (k-major)
__device__ float d_wt2[128 * 128];      // transposed [W2l | W2r] (k-major)

// ---------------- helpers ----------------
__device__ __forceinline__ uint32_t f2tf(float f) {
    uint32_t u; asm("cvt.rna.tf32.f32 %0, %1;" : "=r"(u) : "f"(f)); return u;
}

__device__ __forceinline__ void mma8(float* d, const uint32_t* a, uint2 b) {
    asm volatile(
        "mma.sync.aligned.m16n8k8.row.col.f32.tf32.tf32.f32 "
        "{%0,%1,%2,%3}, {%4,%5,%6,%7}, {%8,%9}, {%0,%1,%2,%3};\n"
        : "+f"(d[0]), "+f"(d[1]), "+f"(d[2]), "+f"(d[3])
        : "r"(a[0]), "r"(a[1]), "r"(a[2]), "r"(a[3]), "r"(b.x), "r"(b.y));
}

// ---------------- CSR build ----------------
__global__ void k_zero() {
    int i = blockIdx.x * blockDim.x + threadIdx.x;
    if (i < NODES) { d_deg[i] = 0; d_cursor[i] = 0; }
}

__global__ void k_hist(const int* __restrict__ dst) {
    int i = blockIdx.x * blockDim.x + threadIdx.x;
    if (i < EDGES) atomicAdd(&d_deg[dst[i]], 1);
}

__global__ void k_scan1() {
    __shared__ int ws[32];
    int i = blockIdx.x * CHUNK + threadIdx.x;
    int lane = threadIdx.x & 31, wid = threadIdx.x >> 5;
    int v = (i < NODES) ? d_deg[i] : 0;
    int x = v;
    #pragma unroll
    for (int o = 1; o < 32; o <<= 1) {
        int y = __shfl_up_sync(0xffffffffu, x, o);
        if (lane >= o) x += y;
    }
    if (lane == 31) ws[wid] = x;
    __syncthreads();
    if (wid == 0) {
        int s = ws[lane];
        #pragma unroll
        for (int o = 1; o < 32; o <<= 1) {
            int y = __shfl_up_sync(0xffffffffu, s, o);
            if (lane >= o) s += y;
        }
        ws[lane] = s;
    }
    __syncthreads();
    int incl = x + (wid > 0 ? ws[wid - 1] : 0);
    if (i < NODES) d_row[i] = incl - v;
    if (threadIdx.x == CHUNK - 1) d_csums[blockIdx.x] = incl;
}

__global__ void k_scan2() {
    if (threadIdx.x == 0) {
        int run = 0;
        for (int c = 0; c < NCHUNK; c++) { int t = d_csums[c]; d_csums[c] = run; run += t; }
    }
}

__global__ void k_scan3() {
    int i = blockIdx.x * blockDim.x + threadIdx.x;
    if (i < NODES) d_row[i] += d_csums[i / CHUNK];
    if (i == 0) d_row[NODES] = EDGES;
}

__global__ void k_scatter(const int* __restrict__ src, const int* __restrict__ dst) {
    int i = blockIdx.x * blockDim.x + threadIdx.x;
    if (i < EDGES) {
        int d = dst[i];
        int o = atomicAdd(&d_cursor[d], 1);
        d_csr[d_row[d] + o] = src[i];
    }
}

// ---------------- weight pre-transpose ----------------
__global__ void k_wt(const float* __restrict__ W1l, const float* __restrict__ W1r,
                     const float* __restrict__ W2l, const float* __restrict__ W2r) {
    int i = blockIdx.x * blockDim.x + threadIdx.x;
    if (i < 256 * 128) {
        int k = i >> 7, n = i & 127;
        d_wt1[i] = (k < 128) ? W1l[n * 128 + k] : W1r[n * 128 + (k - 128)];
    }
    if (i < 128 * 128) {
        int k = i >> 7, n = i & 127;
        d_wt2[i] = (n < 64) ? W2l[n * 128 + k] : W2r[(n - 64) * 128 + k];
    }
}

// ---------------- layer1 aggregation: warp per node ----------------
__global__ void __launch_bounds__(256) k_agg1(const float* __restrict__ x) {
    int gw = (blockIdx.x * blockDim.x + threadIdx.x) >> 5;
    int lane = threadIdx.x & 31;
    if (gw >= NODES) return;
    int s0 = d_row[gw], s1 = d_row[gw + 1];
    const float4* x4 = (const float4*)x;
    float4 acc = make_float4(0.f, 0.f, 0.f, 0.f);
    for (int base = s0; base < s1; base += 32) {
        int rem = s1 - base;
        int sv = (lane < rem) ? d_csr[base + lane] : 0;
        int cnt = rem < 32 ? rem : 32;
        int j = 0;
        for (; j + 4 <= cnt; j += 4) {
            int sa = __shfl_sync(0xffffffffu, sv, j);
            int sb = __shfl_sync(0xffffffffu, sv, j + 1);
            int sc = __shfl_sync(0xffffffffu, sv, j + 2);
            int sd = __shfl_sync(0xffffffffu, sv, j + 3);
            float4 va = x4[sa * 32 + lane];
            float4 vb = x4[sb * 32 + lane];
            float4 vc = x4[sc * 32 + lane];
            float4 vd = x4[sd * 32 + lane];
            acc.x += va.x + vb.x + vc.x + vd.x;
            acc.y += va.y + vb.y + vc.y + vd.y;
            acc.z += va.z + vb.z + vc.z + vd.z;
            acc.w += va.w + vb.w + vc.w + vd.w;
        }
        for (; j < cnt; j++) {
            int s = __shfl_sync(0xffffffffu, sv, j);
            float4 v = x4[s * 32 + lane];
            acc.x += v.x; acc.y += v.y; acc.z += v.z; acc.w += v.w;
        }
    }
    int deg = s1 - s0;
    float sc = 1.0f / (float)(deg > 1 ? deg : 1);
    float4 m = make_float4(acc.x * sc, acc.y * sc, acc.z * sc, acc.w * sc);
    ((float4*)d_mean1)[gw * 32 + lane] = m;
}

// ---------------- TF32 tensor-core GEMMs ----------------
// Tile: 128 nodes x 128 outs per block, 256 threads = 8 warps (4x2),
// warp tile 32x64 = 2 m-frags x 8 n-frags of m16n8k8.
// B resident in smem, paired layout Bp[ks][n][lk][2] for LDS.64 frag loads.
// A double-buffered in 32-wide K chunks, layout Ab[buf][ks][row][8].

extern __shared__ uint32_t smu[];

// GEMM1: h1 = relu([mean1 | x] @ wt1 + b1), K=256 (8 chunks)
__global__ void __launch_bounds__(256) k_gemm1(const float* __restrict__ x,
                                               const float* __restrict__ b1) {
    uint32_t* Bp = smu;              // 32768 words (128 KB)
    uint32_t* Ab = smu + 32768;      // 2 * 4096 words (32 KB)
    int tid = threadIdx.x, lane = tid & 31, w = tid >> 5;
    int wr = w >> 1, wc = w & 1;
    int g = lane >> 2, t = lane & 3;

    for (int i = tid; i < 32768; i += 256) {
        int k = i >> 7, n = i & 127;
        int ks = k >> 3, r = k & 7, half = r >> 2, lk = r & 3;
        Bp[((ks * 128 + n) << 3) + (lk << 1) + half] = f2tf(d_wt1[i]);
    }
    __syncthreads();

    int arow = tid >> 1;             // 0..127
    int acol0 = (tid & 1) << 4;      // 0 or 16

    // hoist bias (per-thread columns are tile-invariant)
    float bx[8], by[8];
    #pragma unroll
    for (int nf = 0; nf < 8; nf++) {
        int cc = wc * 64 + nf * 8 + 2 * t;
        bx[nf] = b1[cc]; by[nf] = b1[cc + 1];
    }

    for (int tile = blockIdx.x; tile < TILES; tile += gridDim.x) {
        int nb = tile << 7;
        float acc[2][8][4];
        #pragma unroll
        for (int mf = 0; mf < 2; mf++)
            #pragma unroll
            for (int nf = 0; nf < 8; nf++)
                #pragma unroll
                for (int q = 0; q < 4; q++) acc[mf][nf][q] = 0.f;

        float4 r4[4];
        auto ldgch = [&](int c) {
            int node = nb + arow;
            const float* src;
            if (c < 4) src = d_mean1 + (size_t)node * 128 + c * 32 + acol0;
            else {
                int nc = node < NODES ? node : NODES - 1;
                src = x + (size_t)nc * 128 + (c - 4) * 32 + acol0;
            }
            #pragma unroll
            for (int i = 0; i < 4; i++) r4[i] = *(const float4*)(src + 4 * i);
        };
        auto stsch = [&](int buf) {
            #pragma unroll
            for (int i = 0; i < 4; i++) {
                int cc = acol0 + 4 * i;
                int ks = cc >> 3, kloc = cc & 7;
                uint32_t* p = Ab + buf * 4096 + ks * 1024 + arow * 8 + kloc;
                uint4 v = make_uint4(f2tf(r4[i].x), f2tf(r4[i].y),
                                     f2tf(r4[i].z), f2tf(r4[i].w));
                *(uint4*)p = v;
            }
        };

        ldgch(0);
        #pragma unroll 1
        for (int c = 0; c < 8; c++) {
            int buf = c & 1;
            stsch(buf);
            __syncthreads();
            if (c < 7) ldgch(c + 1);
            const uint32_t* abase0 = Ab + buf * 4096;
            #pragma unroll
            for (int ks = 0; ks < 4; ks++) {
                const uint32_t* ab = abase0 + ks * 1024;
                uint32_t a[2][4];
                #pragma unroll
                for (int mf = 0; mf < 2; mf++) {
                    int r0 = wr * 32 + mf * 16 + g;
                    a[mf][0] = ab[r0 * 8 + t];
                    a[mf][1] = ab[(r0 + 8) * 8 + t];
                    a[mf][2] = ab[r0 * 8 + t + 4];
                    a[mf][3] = ab[(r0 + 8) * 8 + t + 4];
                }
                int ksg = c * 4 + ks;
                #pragma unroll
                for (int nf = 0; nf < 8; nf++) {
                    int n = wc * 64 + nf * 8 + g;
                    uint2 b = *(const uint2*)(Bp + ((ksg * 128 + n) << 3) + (t << 1));
                    mma8(acc[0][nf], a[0], b);
                    mma8(acc[1][nf], a[1], b);
                }
            }
        }

        #pragma unroll
        for (int mf = 0; mf < 2; mf++) {
            int r0 = nb + wr * 32 + mf * 16 + g;
            #pragma unroll
            for (int nf = 0; nf < 8; nf++) {
                int cc = wc * 64 + nf * 8 + 2 * t;
                float2 v0, v1;
                v0.x = fmaxf(acc[mf][nf][0] + bx[nf], 0.f);
                v0.y = fmaxf(acc[mf][nf][1] + by[nf], 0.f);
                v1.x = fmaxf(acc[mf][nf][2] + bx[nf], 0.f);
                v1.y = fmaxf(acc[mf][nf][3] + by[nf], 0.f);
                *(float2*)(d_h1 + (size_t)r0 * 128 + cc) = v0;
                *(float2*)(d_h1 + (size_t)(r0 + 8) * 128 + cc) = v1;
            }
        }
        __syncthreads();
    }
}

// GEMM2: [pl | pr] = h1 @ wt2, K=128 (4 chunks)
__global__ void __launch_bounds__(256) k_gemm2() {
    uint32_t* Bp = smu;              // 16384 words (64 KB)
    uint32_t* Ab = smu + 16384;      // 2 * 4096 words (32 KB)
    int tid = threadIdx.x, lane = tid & 31, w = tid >> 5;
    int wr = w >> 1, wc = w & 1;
    int g = lane >> 2, t = lane & 3;

    for (int i = tid; i < 16384; i += 256) {
        int k = i >> 7, n = i & 127;
        int ks = k >> 3, r = k & 7, half = r >> 2, lk = r & 3;
        Bp[((ks * 128 + n) << 3) + (lk << 1) + half] = f2tf(d_wt2[i]);
    }
    __syncthreads();

    int arow = tid >> 1;
    int acol0 = (tid & 1) << 4;

    for (int tile = blockIdx.x; tile < TILES; tile += gridDim.x) {
        int nb = tile << 7;
        float acc[2][8][4];
        #pragma unroll
        for (int mf = 0; mf < 2; mf++)
            #pragma unroll
            for (int nf = 0; nf < 8; nf++)
                #pragma unroll
                for (int q = 0; q < 4; q++) acc[mf][nf][q] = 0.f;

        float4 r4[4];
        auto ldgch = [&](int c) {
            const float* src = d_h1 + (size_t)(nb + arow) * 128 + c * 32 + acol0;
            #pragma unroll
            for (int i = 0; i < 4; i++) r4[i] = *(const float4*)(src + 4 * i);
        };
        auto stsch = [&](int buf) {
            #pragma unroll
            for (int i = 0; i < 4; i++) {
                int cc = acol0 + 4 * i;
                int ks = cc >> 3, kloc = cc & 7;
                uint32_t* p = Ab + buf * 4096 + ks * 1024 + arow * 8 + kloc;
                uint4 v = make_uint4(f2tf(r4[i].x), f2tf(r4[i].y),
                                     f2tf(r4[i].z), f2tf(r4[i].w));
                *(uint4*)p = v;
            }
        };

        ldgch(0);
        #pragma unroll 1
        for (int c = 0; c < 4; c++) {
            int buf = c & 1;
            stsch(buf);
            __syncthreads();
            if (c < 3) ldgch(c + 1);
            const uint32_t* abase0 = Ab + buf * 4096;
            #pragma unroll
            for (int ks = 0; ks < 4; ks++) {
                const uint32_t* ab = abase0 + ks * 1024;
                uint32_t a[2][4];
                #pragma unroll
                for (int mf = 0; mf < 2; mf++) {
                    int r0 = wr * 32 + mf * 16 + g;
                    a[mf][0] = ab[r0 * 8 + t];
                    a[mf][1] = ab[(r0 + 8) * 8 + t];
                    a[mf][2] = ab[r0 * 8 + t + 4];
                    a[mf][3] = ab[(r0 + 8) * 8 + t + 4];
                }
                int ksg = c * 4 + ks;
                #pragma unroll
                for (int nf = 0; nf < 8; nf++) {
                    int n = wc * 64 + nf * 8 + g;
                    uint2 b = *(const uint2*)(Bp + ((ksg * 128 + n) << 3) + (t << 1));
                    mma8(acc[0][nf], a[0], b);
                    mma8(acc[1][nf], a[1], b);
                }
            }
        }

        #pragma unroll
        for (int mf = 0; mf < 2; mf++) {
            int r0 = nb + wr * 32 + mf * 16 + g;
            #pragma unroll
            for (int nf = 0; nf < 8; nf++) {
                int cc = wc * 64 + nf * 8 + 2 * t;
                float2 v0 = { acc[mf][nf][0], acc[mf][nf][1] };
                float2 v1 = { acc[mf][nf][2], acc[mf][nf][3] };
                if (wc == 0) {
                    *(float2*)(d_pl + (size_t)r0 * 64 + cc) = v0;
                    *(float2*)(d_pl + (size_t)(r0 + 8) * 64 + cc) = v1;
                } else {
                    *(float2*)(d_pr + (size_t)r0 * 64 + (cc - 64)) = v0;
                    *(float2*)(d_pr + (size_t)(r0 + 8) * 64 + (cc - 64)) = v1;
                }
            }
        }
        __syncthreads();
    }
}

// ---------------- layer2 aggregation + bias + relu + FC, fused ----------------
__global__ void __launch_bounds__(256) k_agg2fc(const float* __restrict__ b2,
                                                const float* __restrict__ Wfc,
                                                const float* __restrict__ bfc,
                                                float* __restrict__ out) {
    int gw = (blockIdx.x * blockDim.x + threadIdx.x) >> 5;
    int lane = threadIdx.x & 31;
    if (gw >= NODES) return;
    int s0 = d_row[gw], s1 = d_row[gw + 1];
    const float2* pl2 = (const float2*)d_pl;
    float a0 = 0.f, a1 = 0.f;
    for (int base = s0; base < s1; base += 32) {
        int rem = s1 - base;
        int sv = (lane < rem) ? d_csr[base + lane] : 0;
        int cnt = rem < 32 ? rem : 32;
        int j = 0;
        for (; j + 4 <= cnt; j += 4) {
            int sa = __shfl_sync(0xffffffffu, sv, j);
            int sb = __shfl_sync(0xffffffffu, sv, j + 1);
            int sc = __shfl_sync(0xffffffffu, sv, j + 2);
            int sd = __shfl_sync(0xffffffffu, sv, j + 3);
            float2 va = pl2[sa * 32 + lane];
            float2 vb = pl2[sb * 32 + lane];
            float2 vc = pl2[sc * 32 + lane];
            float2 vd = pl2[sd * 32 + lane];
            a0 += va.x + vb.x + vc.x + vd.x;
            a1 += va.y + vb.y + vc.y + vd.y;
        }
        for (; j < cnt; j++) {
            int s = __shfl_sync(0xffffffffu, sv, j);
            float2 v = pl2[s * 32 + lane];
            a0 += v.x; a1 += v.y;
        }
    }
    int deg = s1 - s0;
    float sc = 1.0f / (float)(deg > 1 ? deg : 1);
    float2 pr = ((const float2*)d_pr)[gw * 32 + lane];
    float2 bb = ((const float2*)b2)[lane];
    float h0 = fmaxf(a0 * sc + pr.x + bb.x, 0.f);
    float h1 = fmaxf(a1 * sc + pr.y + bb.y, 0.f);
    float2 w0 = ((const float2*)Wfc)[lane];
    float2 w1 = ((const float2*)Wfc)[32 + lane];
    float o0 = h0 * w0.x + h1 * w0.y;
    float o1 = h0 * w1.x + h1 * w1.y;
    #pragma unroll
    for (int o = 16; o; o >>= 1) {
        o0 += __shfl_xor_sync(0xffffffffu, o0, o);
        o1 += __shfl_xor_sync(0xffffffffu, o1, o);
    }
    if (lane == 0) {
        out[2 * gw]     = o0 + bfc[0];
        out[2 * gw + 1] = o1 + bfc[1];
    }
}

// ---------------- launch ----------------
extern "C" void kernel_launch(void* const* d_in, const int* in_sizes, int n_in,
                              void* d_out, int out_size) {
    const float* x   = (const float*)d_in[0];
    const int*   ei  = (const int*)d_in[1];
    const float* W1l = (const float*)d_in[2];
    const float* b1  = (const float*)d_in[3];
    const float* W1r = (const float*)d_in[4];
    const float* W2l = (const float*)d_in[5];
    const float* b2  = (const float*)d_in[6];
    const float* W2r = (const float*)d_in[7];
    const float* Wfc = (const float*)d_in[8];
    const float* bfc = (const float*)d_in[9];
    float* out = (float*)d_out;
    const int* src = ei;
    const int* dst = ei + EDGES;

    const int SMEM_G1 = (32768 + 2 * 4096) * 4;   // 163,840 B
    const int SMEM_G2 = (16384 + 2 * 4096) * 4;   //  98,304 B
    cudaFuncSetAttribute(k_gemm1, cudaFuncAttributeMaxDynamicSharedMemorySize, SMEM_G1);
    cudaFuncSetAttribute(k_gemm2, cudaFuncAttributeMaxDynamicSharedMemorySize, SMEM_G2);

    k_zero<<<(NODES + 255) / 256, 256>>>();
    k_wt<<<(256 * 128 + 255) / 256, 256>>>(W1l, W1r, W2l, W2r);
    k_hist<<<(EDGES + 255) / 256, 256>>>(dst);
    k_scan1<<<NCHUNK, CHUNK>>>();
    k_scan2<<<1, 32>>>();
    k_scan3<<<(NODES + 255) / 256, 256>>>();
    k_scatter<<<(EDGES + 255) / 256, 256>>>(src, dst);
    k_agg1<<<(NODES * 32 + 255) / 256, 256>>>(x);
    k_gemm1<<<148, 256, SMEM_G1>>>(x, b1);
    k_gemm2<<<148, 256, SMEM_G2>>>();
    k_agg2fc<<<(NODES * 32 + 255) / 256, 256>>>(b2, Wfc, bfc, out);
}